// round 9
// baseline (speedup 1.0000x reference)
#include <cuda_runtime.h>

#define NHEAD 8
#define SEQ   4096
#define DH    8
#define PAIRS (SEQ / 2)          // 2048 packed t-pairs per head
#define CAP   16                 // deferred-entry slots per (thread,row)
#define WIN   20.0f              // window: dropped terms < 4096*e^-20 ~ 8e-6

// Scratch (__device__ globals; no allocations allowed).
// INTERLEAVED pair-packed fp32 effective keys: pair p_g of head g at index
//   g*PAIRS + (p_g & 511)*4 + (p_g >> 9)
// so quad lane q (owning pairs [q*512,(q+1)*512)) reads zs[p*4+q]: the quad's
// 4 reads are 64 B contiguous + row broadcast.
//  zA word: (zx_t, zx_t1, zy_t, zy_t1),  zB word: (zz_t, zz_t1, zw_t, zw_t1)
// where z_t = SCALE * ( Wq^T Wk x2_t , bq . Wk x2_t ).
__device__ float4 g_zA[NHEAD * PAIRS];
__device__ float4 g_zB[NHEAD * PAIRS];
__device__ float  g_v [NHEAD * SEQ * DH];   // v[g][t][h] = Wv x1 + bv

// ---------------------------------------------------------------------------
// Packed f32x2 helpers
// ---------------------------------------------------------------------------
__device__ __forceinline__ unsigned long long fma2(unsigned long long a,
                                                   unsigned long long b,
                                                   unsigned long long c) {
    unsigned long long d;
    asm("fma.rn.f32x2 %0, %1, %2, %3;" : "=l"(d) : "l"(a), "l"(b), "l"(c));
    return d;
}
__device__ __forceinline__ unsigned long long pack2(float x, float y) {
    unsigned long long r;
    asm("mov.b64 %0, {%1, %2};" : "=l"(r) : "f"(x), "f"(y));
    return r;
}
__device__ __forceinline__ void unpack2(unsigned long long v, float& x, float& y) {
    asm("mov.b64 {%0, %1}, %2;" : "=f"(x), "=f"(y) : "l"(v));
}

// ---------------------------------------------------------------------------
// Precompute: one thread per (g, pair p) -> writes interleaved zA/zB + v rows.
// ---------------------------------------------------------------------------
__device__ __forceinline__ float4 eff_key(const float X2[3],
                                          const float* __restrict__ Wq,
                                          const float* __restrict__ bq,
                                          const float* __restrict__ Wk) {
    const float SCALEF = 1448.1546878700492f;  // 2^10.5
    float y0 = 0.f, y1 = 0.f, y2 = 0.f, w = 0.f;
#pragma unroll
    for (int h = 0; h < 8; h++) {
        float u = fmaf(Wk[h * 3 + 0], X2[0],
                  fmaf(Wk[h * 3 + 1], X2[1], Wk[h * 3 + 2] * X2[2]));
        y0 = fmaf(Wq[h * 3 + 0], u, y0);
        y1 = fmaf(Wq[h * 3 + 1], u, y1);
        y2 = fmaf(Wq[h * 3 + 2], u, y2);
        w  = fmaf(bq[h], u, w);
    }
    return make_float4(SCALEF * y0, SCALEF * y1, SCALEF * y2, SCALEF * w);
}

__global__ void precompute_kernel(const float* __restrict__ x1,
                                  const float* __restrict__ x2,
                                  const float* __restrict__ Wq,
                                  const float* __restrict__ bq,
                                  const float* __restrict__ Wk,
                                  const float* __restrict__ Wv,
                                  const float* __restrict__ bv) {
    int i = blockIdx.x * blockDim.x + threadIdx.x;   // i = g*PAIRS + p
    if (i >= NHEAD * PAIRS) return;
    const int g = i >> 11;
    const int p = i & (PAIRS - 1);
    const int r0 = g * SEQ + 2 * p;

    float X2a[3], X2b[3], X1a[3], X1b[3];
#pragma unroll
    for (int j = 0; j < 3; j++) {
        X2a[j] = x2[r0 * 3 + j];       X2b[j] = x2[(r0 + 1) * 3 + j];
        X1a[j] = x1[r0 * 3 + j];       X1b[j] = x1[(r0 + 1) * 3 + j];
    }
    const float4 za = eff_key(X2a, Wq, bq, Wk);
    const float4 zb = eff_key(X2b, Wq, bq, Wk);

    const int dst = g * PAIRS + ((p & 511) << 2) + (p >> 9);   // interleaved
    g_zA[dst] = make_float4(za.x, zb.x, za.y, zb.y);
    g_zB[dst] = make_float4(za.z, zb.z, za.w, zb.w);

#pragma unroll
    for (int h = 0; h < 8; h++) {
        g_v[(size_t)r0 * 8 + h] =
            fmaf(Wv[h * 3 + 0], X1a[0], fmaf(Wv[h * 3 + 1], X1a[1],
            fmaf(Wv[h * 3 + 2], X1a[2], bv[h])));
        g_v[(size_t)(r0 + 1) * 8 + h] =
            fmaf(Wv[h * 3 + 0], X1b[0], fmaf(Wv[h * 3 + 1], X1b[1],
            fmaf(Wv[h * 3 + 2], X1b[2], bv[h])));
    }
}

// ---------------------------------------------------------------------------
// Threefry2x32, partitionable mode: word(i) = x0^x1 of counter (0, i),
// key (0, 42). keep <=> MSB == 0.
// ---------------------------------------------------------------------------
__device__ __forceinline__ unsigned rotl32(unsigned x, int r) {
    return __funnelshift_l(x, x, r);
}
__device__ __forceinline__ unsigned threefry_word(unsigned idx) {
    const unsigned K1 = 42u;
    const unsigned K2 = 0x1BD11BF0u;
    unsigned x0 = 0u;
    unsigned x1 = idx + K1;
#define TF_R(r)  { x0 += x1; x1 = rotl32(x1, r); x1 ^= x0; }
#define TF_G(a,b,c,d,j0,j1) TF_R(a) TF_R(b) TF_R(c) TF_R(d) x0 += (j0); x1 += (j1);
    TF_G(13, 15, 26,  6, K1,       K2 + 1u)
    TF_G(17, 29, 16, 24, K2,       0u + 2u)
    TF_G(13, 15, 26,  6, 0u,       K1 + 3u)
    TF_G(17, 29, 16, 24, K1,       K2 + 4u)
    TF_G(13, 15, 26,  6, K2,       0u + 5u)
#undef TF_G
#undef TF_R
    return x0 ^ x1;
}

// Exact fp32 re-score of local t (0..1023) for quad lane q from smem.
// Same FMA chain as the scan -> bit-identical values.
__device__ __forceinline__ float score_at(const float4* __restrict__ zs, int q,
                                          int tloc, float a, float b, float c) {
    const int idx = ((tloc >> 1) << 2) + q;
    const float4 A = zs[idx];
    const float4 B = zs[PAIRS + idx];
    const bool odd = (tloc & 1);
    const float zx = odd ? A.y : A.x;
    const float zy = odd ? A.w : A.z;
    const float zz = odd ? B.y : B.x;
    const float zw = odd ? B.w : B.z;
    return fmaf(a, zx, fmaf(b, zy, fmaf(c, zz, zw)));
}

__device__ __forceinline__ void emit32(unsigned short* buf, int& cnt,
                                       const float4* __restrict__ zs, int q,
                                       float a, float b, float c,
                                       float m, int tl) {
    if (cnt == CAP) {                       // prune entries below current window
        int k = 0;
        for (int i = 0; i < CAP; i++) {
            const int t2 = buf[i];
            if (score_at(zs, q, t2, a, b, c) > m - WIN)
                buf[k++] = (unsigned short)t2;
        }
        cnt = k;
        if (cnt == CAP) cnt = CAP - 1;      // ~impossible; keep newest
    }
    buf[cnt++] = (unsigned short)tl;
}

// Phase 2 + quad merge + output for one row. Uniform control at shfl points.
__device__ __forceinline__ void finalize_row(const float4* __restrict__ zs,
                                             const unsigned short* buf, int cnt,
                                             float m, int q, int g, int row,
                                             float a, float b, float c,
                                             float* __restrict__ out) {
    const float* vg = g_v + ((size_t)g * SEQ + (size_t)(q << 10)) * DH;
    const unsigned rowbase = ((unsigned)row << 12) + (unsigned)(q << 10);
    const float M = m;
    float l = 0.f;
    float acc0 = 0.f, acc1 = 0.f, acc2 = 0.f, acc3 = 0.f;
    float acc4 = 0.f, acc5 = 0.f, acc6 = 0.f, acc7 = 0.f;
    for (int i = 0; i < cnt; i++) {
        const int tloc = buf[i];
        const float sc = score_at(zs, q, tloc, a, b, c);
        if (sc > M - WIN) {
            const float e = __expf(sc - M);
            l += e;                                    // denominator: mask-free
            const unsigned w = threefry_word(rowbase + (unsigned)tloc);
            if (!(w & 0x80000000u)) {                  // keep (u < 0.5)
                const float4* vp =
                    reinterpret_cast<const float4*>(vg + (size_t)tloc * DH);
                const float4 va = vp[0];
                const float4 vb = vp[1];
                acc0 = fmaf(e, va.x, acc0);
                acc1 = fmaf(e, va.y, acc1);
                acc2 = fmaf(e, va.z, acc2);
                acc3 = fmaf(e, va.w, acc3);
                acc4 = fmaf(e, vb.x, acc4);
                acc5 = fmaf(e, vb.y, acc5);
                acc6 = fmaf(e, vb.z, acc6);
                acc7 = fmaf(e, vb.w, acc7);
            }
        }
    }
    // quad merge (lanes xor 1, 2 share a row)
    float Mq = M;
    Mq = fmaxf(Mq, __shfl_xor_sync(0xffffffffu, Mq, 1));
    Mq = fmaxf(Mq, __shfl_xor_sync(0xffffffffu, Mq, 2));
    const float f = __expf(M - Mq);
    l *= f;
    acc0 *= f; acc1 *= f; acc2 *= f; acc3 *= f;
    acc4 *= f; acc5 *= f; acc6 *= f; acc7 *= f;
#pragma unroll
    for (int d = 1; d <= 2; d <<= 1) {
        l    += __shfl_xor_sync(0xffffffffu, l,    d);
        acc0 += __shfl_xor_sync(0xffffffffu, acc0, d);
        acc1 += __shfl_xor_sync(0xffffffffu, acc1, d);
        acc2 += __shfl_xor_sync(0xffffffffu, acc2, d);
        acc3 += __shfl_xor_sync(0xffffffffu, acc3, d);
        acc4 += __shfl_xor_sync(0xffffffffu, acc4, d);
        acc5 += __shfl_xor_sync(0xffffffffu, acc5, d);
        acc6 += __shfl_xor_sync(0xffffffffu, acc6, d);
        acc7 += __shfl_xor_sync(0xffffffffu, acc7, d);
    }
    const float inv = 2.0f / l;                         // dropout 1/(1-p) = 2
    const float oc[8] = {acc0 * inv, acc1 * inv, acc2 * inv, acc3 * inv,
                         acc4 * inv, acc5 * inv, acc6 * inv, acc7 * inv};
    float2* op = reinterpret_cast<float2*>(out + (size_t)row * DH);
    op[q] = make_float2(oc[2 * q], oc[2 * q + 1]);
}

// ---------------------------------------------------------------------------
// Main kernel. Block = 128 threads: 32 row-slots x quad(4). Each thread owns
// TWO rows (s0, s0+32) and quad lane q's t-quarter [q*1024,(q+1)*1024).
// Phase 1 (hot): fp32 packed scores from interleaved smem (each LDS.128 feeds
// both rows), running max, emit qualifying t's to smem buffers.
// Phase 2: exact finalize per row (R6 logic verbatim).
// ---------------------------------------------------------------------------
__global__ void __launch_bounds__(128) attn_kernel(const float* __restrict__ x1,
                                                   float* __restrict__ out) {
    extern __shared__ char smem_raw[];
    float4* zs = reinterpret_cast<float4*>(smem_raw);             // 64 KB
    unsigned short* tb = reinterpret_cast<unsigned short*>(smem_raw + 65536);
    const int g = blockIdx.y;

    for (int i = threadIdx.x; i < PAIRS; i += 128) {
        zs[i]         = g_zA[g * PAIRS + i];   // linear copy keeps interleave
        zs[PAIRS + i] = g_zB[g * PAIRS + i];
    }
    __syncthreads();

    const int q     = threadIdx.x & 3;
    const int rslot = threadIdx.x >> 2;                 // 0..31
    const int s0    = blockIdx.x * 64 + rslot;
    const int s1    = s0 + 32;
    const int row0  = g * SEQ + s0;
    const int row1  = g * SEQ + s1;

    const float a0 = x1[row0 * 3 + 0], b0 = x1[row0 * 3 + 1], c0 = x1[row0 * 3 + 2];
    const float a1 = x1[row1 * 3 + 0], b1 = x1[row1 * 3 + 1], c1 = x1[row1 * 3 + 2];
    const unsigned long long aa0 = pack2(a0, a0), bb0 = pack2(b0, b0), cc0 = pack2(c0, c0);
    const unsigned long long aa1 = pack2(a1, a1), bb1 = pack2(b1, b1), cc1 = pack2(c1, c1);

    unsigned short* buf0 = tb + threadIdx.x * (2 * CAP);
    unsigned short* buf1 = buf0 + CAP;
    int cnt0 = 0, cnt1 = 0;

    const ulonglong2* ZA = reinterpret_cast<const ulonglong2*>(zs) + q;
    const ulonglong2* ZB = ZA + PAIRS;

    float m0 = -3.0e38f, m1 = -3.0e38f;

    for (int p = 0; p < 512; p += 4) {         // 8 t's x 2 rows per iteration
        const ulonglong2 A0 = ZA[(p + 0) << 2], B0 = ZB[(p + 0) << 2];
        const ulonglong2 A1 = ZA[(p + 1) << 2], B1 = ZB[(p + 1) << 2];
        const ulonglong2 A2 = ZA[(p + 2) << 2], B2 = ZB[(p + 2) << 2];
        const ulonglong2 A3 = ZA[(p + 3) << 2], B3 = ZB[(p + 3) << 2];

        // row 0 scores
        const unsigned long long R00 = fma2(aa0, A0.x, fma2(bb0, A0.y, fma2(cc0, B0.x, B0.y)));
        const unsigned long long R01 = fma2(aa0, A1.x, fma2(bb0, A1.y, fma2(cc0, B1.x, B1.y)));
        const unsigned long long R02 = fma2(aa0, A2.x, fma2(bb0, A2.y, fma2(cc0, B2.x, B2.y)));
        const unsigned long long R03 = fma2(aa0, A3.x, fma2(bb0, A3.y, fma2(cc0, B3.x, B3.y)));
        // row 1 scores
        const unsigned long long R10 = fma2(aa1, A0.x, fma2(bb1, A0.y, fma2(cc1, B0.x, B0.y)));
        const unsigned long long R11 = fma2(aa1, A1.x, fma2(bb1, A1.y, fma2(cc1, B1.x, B1.y)));
        const unsigned long long R12 = fma2(aa1, A2.x, fma2(bb1, A2.y, fma2(cc1, B2.x, B2.y)));
        const unsigned long long R13 = fma2(aa1, A3.x, fma2(bb1, A3.y, fma2(cc1, B3.x, B3.y)));

        float u0, u1, u2, u3, u4, u5, u6, u7;
        unpack2(R00, u0, u1); unpack2(R01, u2, u3);
        unpack2(R02, u4, u5); unpack2(R03, u6, u7);
        const float pm0 = fmaxf(fmaxf(fmaxf(u0, u1), fmaxf(u2, u3)),
                                fmaxf(fmaxf(u4, u5), fmaxf(u6, u7)));

        float w0, w1, w2, w3, w4, w5, w6, w7;
        unpack2(R10, w0, w1); unpack2(R11, w2, w3);
        unpack2(R12, w4, w5); unpack2(R13, w6, w7);
        const float pm1 = fmaxf(fmaxf(fmaxf(w0, w1), fmaxf(w2, w3)),
                                fmaxf(fmaxf(w4, w5), fmaxf(w6, w7)));

        if (pm0 > m0 - WIN) {                  // cold path row 0
            m0 = fmaxf(m0, pm0);
            const float sv[8] = {u0, u1, u2, u3, u4, u5, u6, u7};
#pragma unroll
            for (int j = 0; j < 8; j++)
                if (sv[j] > m0 - WIN)
                    emit32(buf0, cnt0, zs, q, a0, b0, c0, m0, 2 * p + j);
        }
        if (pm1 > m1 - WIN) {                  // cold path row 1
            m1 = fmaxf(m1, pm1);
            const float sv[8] = {w0, w1, w2, w3, w4, w5, w6, w7};
#pragma unroll
            for (int j = 0; j < 8; j++)
                if (sv[j] > m1 - WIN)
                    emit32(buf1, cnt1, zs, q, a1, b1, c1, m1, 2 * p + j);
        }
    }

    finalize_row(zs, buf0, cnt0, m0, q, g, row0, a0, b0, c0, out);
    finalize_row(zs, buf1, cnt1, m1, q, g, row1, a1, b1, c1, out);
}

// ---------------------------------------------------------------------------
extern "C" void kernel_launch(void* const* d_in, const int* in_sizes, int n_in,
                              void* d_out, int out_size) {
    const float* x1 = (const float*)d_in[0];
    const float* x2 = (const float*)d_in[1];
    const float* Wq = (const float*)d_in[2];
    const float* bq = (const float*)d_in[3];
    const float* Wk = (const float*)d_in[4];
    // d_in[5] = bk: per-row constant -> cancels in softmax
    const float* Wv = (const float*)d_in[6];
    const float* bv = (const float*)d_in[7];
    float* out = (float*)d_out;

    precompute_kernel<<<(NHEAD * PAIRS + 255) / 256, 256>>>(x1, x2, Wq, bq, Wk, Wv, bv);

    const int smem = 2 * PAIRS * (int)sizeof(float4)              // 64 KB z
                   + 128 * 2 * CAP * (int)sizeof(unsigned short); // 8 KB buffers
    cudaFuncSetAttribute(attn_kernel, cudaFuncAttributeMaxDynamicSharedMemorySize, smem);
    dim3 grid(SEQ / 64, NHEAD);
    attn_kernel<<<grid, 128, smem>>>(x1, out);
}

// round 10
// speedup vs baseline: 1.4510x; 1.4510x over previous
#include <cuda_runtime.h>

#define NHEAD 8
#define SEQ   4096
#define DH    8
#define PAIRS (SEQ / 2)          // 2048 packed t-pairs per head
#define CAP   10                 // deferred-entry slots per (thread,row)
#define WIN   20.0f              // window: dropped terms < 4096*e^-20 ~ 8e-6

// Scratch (__device__ globals; no allocations allowed).
// INTERLEAVED pair-packed fp32 effective keys: pair p_g of head g at index
//   g*PAIRS + (p_g & 511)*4 + (p_g >> 9)
// so quad lane q (owning pairs [q*512,(q+1)*512)) reads zs[p*4+q]: the quad's
// 4 reads are 64 B contiguous + row broadcast -> conflict-free.
//  zA word: (zx_t, zx_t1, zy_t, zy_t1),  zB word: (zz_t, zz_t1, zw_t, zw_t1)
// where z_t = SCALE * ( Wq^T Wk x2_t , bq . Wk x2_t ).
__device__ float4 g_zA[NHEAD * PAIRS];
__device__ float4 g_zB[NHEAD * PAIRS];
__device__ float  g_v [NHEAD * SEQ * DH];   // v[g][t][h] = Wv x1 + bv

// ---------------------------------------------------------------------------
// Packed f32x2 helpers
// ---------------------------------------------------------------------------
__device__ __forceinline__ unsigned long long fma2(unsigned long long a,
                                                   unsigned long long b,
                                                   unsigned long long c) {
    unsigned long long d;
    asm("fma.rn.f32x2 %0, %1, %2, %3;" : "=l"(d) : "l"(a), "l"(b), "l"(c));
    return d;
}
__device__ __forceinline__ unsigned long long pack2(float x, float y) {
    unsigned long long r;
    asm("mov.b64 %0, {%1, %2};" : "=l"(r) : "f"(x), "f"(y));
    return r;
}
__device__ __forceinline__ void unpack2(unsigned long long v, float& x, float& y) {
    asm("mov.b64 {%0, %1}, %2;" : "=f"(x), "=f"(y) : "l"(v));
}

// ---------------------------------------------------------------------------
// Precompute: one thread per (g, pair p) -> writes interleaved zA/zB + v rows.
// ---------------------------------------------------------------------------
__device__ __forceinline__ float4 eff_key(const float X2[3],
                                          const float* __restrict__ Wq,
                                          const float* __restrict__ bq,
                                          const float* __restrict__ Wk) {
    const float SCALEF = 1448.1546878700492f;  // 2^10.5
    float y0 = 0.f, y1 = 0.f, y2 = 0.f, w = 0.f;
#pragma unroll
    for (int h = 0; h < 8; h++) {
        float u = fmaf(Wk[h * 3 + 0], X2[0],
                  fmaf(Wk[h * 3 + 1], X2[1], Wk[h * 3 + 2] * X2[2]));
        y0 = fmaf(Wq[h * 3 + 0], u, y0);
        y1 = fmaf(Wq[h * 3 + 1], u, y1);
        y2 = fmaf(Wq[h * 3 + 2], u, y2);
        w  = fmaf(bq[h], u, w);
    }
    return make_float4(SCALEF * y0, SCALEF * y1, SCALEF * y2, SCALEF * w);
}

__global__ void precompute_kernel(const float* __restrict__ x1,
                                  const float* __restrict__ x2,
                                  const float* __restrict__ Wq,
                                  const float* __restrict__ bq,
                                  const float* __restrict__ Wk,
                                  const float* __restrict__ Wv,
                                  const float* __restrict__ bv) {
    int i = blockIdx.x * blockDim.x + threadIdx.x;   // i = g*PAIRS + p
    if (i >= NHEAD * PAIRS) return;
    const int g = i >> 11;
    const int p = i & (PAIRS - 1);
    const int r0 = g * SEQ + 2 * p;

    float X2a[3], X2b[3], X1a[3], X1b[3];
#pragma unroll
    for (int j = 0; j < 3; j++) {
        X2a[j] = x2[r0 * 3 + j];       X2b[j] = x2[(r0 + 1) * 3 + j];
        X1a[j] = x1[r0 * 3 + j];       X1b[j] = x1[(r0 + 1) * 3 + j];
    }
    const float4 za = eff_key(X2a, Wq, bq, Wk);
    const float4 zb = eff_key(X2b, Wq, bq, Wk);

    const int dst = g * PAIRS + ((p & 511) << 2) + (p >> 9);   // interleaved
    g_zA[dst] = make_float4(za.x, zb.x, za.y, zb.y);
    g_zB[dst] = make_float4(za.z, zb.z, za.w, zb.w);

#pragma unroll
    for (int h = 0; h < 8; h++) {
        g_v[(size_t)r0 * 8 + h] =
            fmaf(Wv[h * 3 + 0], X1a[0], fmaf(Wv[h * 3 + 1], X1a[1],
            fmaf(Wv[h * 3 + 2], X1a[2], bv[h])));
        g_v[(size_t)(r0 + 1) * 8 + h] =
            fmaf(Wv[h * 3 + 0], X1b[0], fmaf(Wv[h * 3 + 1], X1b[1],
            fmaf(Wv[h * 3 + 2], X1b[2], bv[h])));
    }
}

// ---------------------------------------------------------------------------
// Threefry2x32, partitionable mode: word(i) = x0^x1 of counter (0, i),
// key (0, 42). keep <=> MSB == 0.
// ---------------------------------------------------------------------------
__device__ __forceinline__ unsigned rotl32(unsigned x, int r) {
    return __funnelshift_l(x, x, r);
}
__device__ __forceinline__ unsigned threefry_word(unsigned idx) {
    const unsigned K1 = 42u;
    const unsigned K2 = 0x1BD11BF0u;
    unsigned x0 = 0u;
    unsigned x1 = idx + K1;
#define TF_R(r)  { x0 += x1; x1 = rotl32(x1, r); x1 ^= x0; }
#define TF_G(a,b,c,d,j0,j1) TF_R(a) TF_R(b) TF_R(c) TF_R(d) x0 += (j0); x1 += (j1);
    TF_G(13, 15, 26,  6, K1,       K2 + 1u)
    TF_G(17, 29, 16, 24, K2,       0u + 2u)
    TF_G(13, 15, 26,  6, 0u,       K1 + 3u)
    TF_G(17, 29, 16, 24, K1,       K2 + 4u)
    TF_G(13, 15, 26,  6, K2,       0u + 5u)
#undef TF_G
#undef TF_R
    return x0 ^ x1;
}

// Exact fp32 re-score of local t (0..1023) for quad lane q from smem.
// Same FMA chain as the scan -> bit-identical values.
__device__ __forceinline__ float score_at(const float4* __restrict__ zs, int q,
                                          int tloc, float a, float b, float c) {
    const int idx = ((tloc >> 1) << 2) + q;
    const float4 A = zs[idx];
    const float4 B = zs[PAIRS + idx];
    const bool odd = (tloc & 1);
    const float zx = odd ? A.y : A.x;
    const float zy = odd ? A.w : A.z;
    const float zz = odd ? B.y : B.x;
    const float zw = odd ? B.w : B.z;
    return fmaf(a, zx, fmaf(b, zy, fmaf(c, zz, zw)));
}

__device__ __forceinline__ void emit32(unsigned short* buf, int& cnt,
                                       const float4* __restrict__ zs, int q,
                                       float a, float b, float c,
                                       float m, int tl) {
    if (cnt == CAP) {                       // prune entries below current window
        int k = 0;
        for (int i = 0; i < CAP; i++) {
            const int t2 = buf[i];
            if (score_at(zs, q, t2, a, b, c) > m - WIN)
                buf[k++] = (unsigned short)t2;
        }
        cnt = k;
        if (cnt == CAP) cnt = CAP - 1;      // ~impossible; keep newest
    }
    buf[cnt++] = (unsigned short)tl;
}

// Phase 2 + quad merge + output for one row. Uniform control at shfl points.
__device__ __forceinline__ void finalize_row(const float4* __restrict__ zs,
                                             const unsigned short* buf, int cnt,
                                             float m, int q, int g, int row,
                                             float a, float b, float c,
                                             float* __restrict__ out) {
    const float* vg = g_v + ((size_t)g * SEQ + (size_t)(q << 10)) * DH;
    const unsigned rowbase = ((unsigned)row << 12) + (unsigned)(q << 10);
    const float M = m;
    float l = 0.f;
    float acc0 = 0.f, acc1 = 0.f, acc2 = 0.f, acc3 = 0.f;
    float acc4 = 0.f, acc5 = 0.f, acc6 = 0.f, acc7 = 0.f;
    for (int i = 0; i < cnt; i++) {
        const int tloc = buf[i];
        const float sc = score_at(zs, q, tloc, a, b, c);
        if (sc > M - WIN) {
            const float e = __expf(sc - M);
            l += e;                                    // denominator: mask-free
            const unsigned w = threefry_word(rowbase + (unsigned)tloc);
            if (!(w & 0x80000000u)) {                  // keep (u < 0.5)
                const float4* vp =
                    reinterpret_cast<const float4*>(vg + (size_t)tloc * DH);
                const float4 va = vp[0];
                const float4 vb = vp[1];
                acc0 = fmaf(e, va.x, acc0);
                acc1 = fmaf(e, va.y, acc1);
                acc2 = fmaf(e, va.z, acc2);
                acc3 = fmaf(e, va.w, acc3);
                acc4 = fmaf(e, vb.x, acc4);
                acc5 = fmaf(e, vb.y, acc5);
                acc6 = fmaf(e, vb.z, acc6);
                acc7 = fmaf(e, vb.w, acc7);
            }
        }
    }
    // quad merge (lanes xor 1, 2 share a row)
    float Mq = M;
    Mq = fmaxf(Mq, __shfl_xor_sync(0xffffffffu, Mq, 1));
    Mq = fmaxf(Mq, __shfl_xor_sync(0xffffffffu, Mq, 2));
    const float f = __expf(M - Mq);
    l *= f;
    acc0 *= f; acc1 *= f; acc2 *= f; acc3 *= f;
    acc4 *= f; acc5 *= f; acc6 *= f; acc7 *= f;
#pragma unroll
    for (int d = 1; d <= 2; d <<= 1) {
        l    += __shfl_xor_sync(0xffffffffu, l,    d);
        acc0 += __shfl_xor_sync(0xffffffffu, acc0, d);
        acc1 += __shfl_xor_sync(0xffffffffu, acc1, d);
        acc2 += __shfl_xor_sync(0xffffffffu, acc2, d);
        acc3 += __shfl_xor_sync(0xffffffffu, acc3, d);
        acc4 += __shfl_xor_sync(0xffffffffu, acc4, d);
        acc5 += __shfl_xor_sync(0xffffffffu, acc5, d);
        acc6 += __shfl_xor_sync(0xffffffffu, acc6, d);
        acc7 += __shfl_xor_sync(0xffffffffu, acc7, d);
    }
    const float inv = 2.0f / l;                         // dropout 1/(1-p) = 2
    const float oc[8] = {acc0 * inv, acc1 * inv, acc2 * inv, acc3 * inv,
                         acc4 * inv, acc5 * inv, acc6 * inv, acc7 * inv};
    float2* op = reinterpret_cast<float2*>(out + (size_t)row * DH);
    op[q] = make_float2(oc[2 * q], oc[2 * q + 1]);
}

// ---------------------------------------------------------------------------
// Main kernel. Block = 256 threads: 64 row-slots x quad(4). Each thread owns
// TWO rows (s0, s0+64) and quad lane q's t-quarter [q*1024,(q+1)*1024).
// Phase 1 (hot): fp32 packed scores from interleaved smem (each LDS.128 feeds
// both rows), running max, emit qualifying t's to smem buffers.
// Phase 2: exact finalize per row. smem = 64 KB z + 10 KB buf -> 3 CTAs/SM.
// ---------------------------------------------------------------------------
__global__ void __launch_bounds__(256) attn_kernel(const float* __restrict__ x1,
                                                   float* __restrict__ out) {
    extern __shared__ char smem_raw[];
    float4* zs = reinterpret_cast<float4*>(smem_raw);             // 64 KB
    unsigned short* tb = reinterpret_cast<unsigned short*>(smem_raw + 65536);
    const int g = blockIdx.y;

    for (int i = threadIdx.x; i < PAIRS; i += 256) {
        zs[i]         = g_zA[g * PAIRS + i];   // linear copy keeps interleave
        zs[PAIRS + i] = g_zB[g * PAIRS + i];
    }
    __syncthreads();

    const int q     = threadIdx.x & 3;
    const int rslot = threadIdx.x >> 2;                 // 0..63
    const int s0    = blockIdx.x * 128 + rslot;
    const int s1    = s0 + 64;
    const int row0  = g * SEQ + s0;
    const int row1  = g * SEQ + s1;

    const float a0 = x1[row0 * 3 + 0], b0 = x1[row0 * 3 + 1], c0 = x1[row0 * 3 + 2];
    const float a1 = x1[row1 * 3 + 0], b1 = x1[row1 * 3 + 1], c1 = x1[row1 * 3 + 2];
    const unsigned long long aa0 = pack2(a0, a0), bb0 = pack2(b0, b0), cc0 = pack2(c0, c0);
    const unsigned long long aa1 = pack2(a1, a1), bb1 = pack2(b1, b1), cc1 = pack2(c1, c1);

    unsigned short* buf0 = tb + threadIdx.x * (2 * CAP);
    unsigned short* buf1 = buf0 + CAP;
    int cnt0 = 0, cnt1 = 0;

    const ulonglong2* ZA = reinterpret_cast<const ulonglong2*>(zs) + q;
    const ulonglong2* ZB = ZA + PAIRS;

    float m0 = -3.0e38f, m1 = -3.0e38f;

    for (int p = 0; p < 512; p += 4) {         // 8 t's x 2 rows per iteration
        const ulonglong2 A0 = ZA[(p + 0) << 2], B0 = ZB[(p + 0) << 2];
        const ulonglong2 A1 = ZA[(p + 1) << 2], B1 = ZB[(p + 1) << 2];
        const ulonglong2 A2 = ZA[(p + 2) << 2], B2 = ZB[(p + 2) << 2];
        const ulonglong2 A3 = ZA[(p + 3) << 2], B3 = ZB[(p + 3) << 2];

        // row 0 scores
        const unsigned long long R00 = fma2(aa0, A0.x, fma2(bb0, A0.y, fma2(cc0, B0.x, B0.y)));
        const unsigned long long R01 = fma2(aa0, A1.x, fma2(bb0, A1.y, fma2(cc0, B1.x, B1.y)));
        const unsigned long long R02 = fma2(aa0, A2.x, fma2(bb0, A2.y, fma2(cc0, B2.x, B2.y)));
        const unsigned long long R03 = fma2(aa0, A3.x, fma2(bb0, A3.y, fma2(cc0, B3.x, B3.y)));
        // row 1 scores
        const unsigned long long R10 = fma2(aa1, A0.x, fma2(bb1, A0.y, fma2(cc1, B0.x, B0.y)));
        const unsigned long long R11 = fma2(aa1, A1.x, fma2(bb1, A1.y, fma2(cc1, B1.x, B1.y)));
        const unsigned long long R12 = fma2(aa1, A2.x, fma2(bb1, A2.y, fma2(cc1, B2.x, B2.y)));
        const unsigned long long R13 = fma2(aa1, A3.x, fma2(bb1, A3.y, fma2(cc1, B3.x, B3.y)));

        float u0, u1, u2, u3, u4, u5, u6, u7;
        unpack2(R00, u0, u1); unpack2(R01, u2, u3);
        unpack2(R02, u4, u5); unpack2(R03, u6, u7);
        const float pm0 = fmaxf(fmaxf(fmaxf(u0, u1), fmaxf(u2, u3)),
                                fmaxf(fmaxf(u4, u5), fmaxf(u6, u7)));

        float w0, w1, w2, w3, w4, w5, w6, w7;
        unpack2(R10, w0, w1); unpack2(R11, w2, w3);
        unpack2(R12, w4, w5); unpack2(R13, w6, w7);
        const float pm1 = fmaxf(fmaxf(fmaxf(w0, w1), fmaxf(w2, w3)),
                                fmaxf(fmaxf(w4, w5), fmaxf(w6, w7)));

        if (pm0 > m0 - WIN) {                  // cold path row 0
            m0 = fmaxf(m0, pm0);
            const float sv[8] = {u0, u1, u2, u3, u4, u5, u6, u7};
#pragma unroll
            for (int j = 0; j < 8; j++)
                if (sv[j] > m0 - WIN)
                    emit32(buf0, cnt0, zs, q, a0, b0, c0, m0, 2 * p + j);
        }
        if (pm1 > m1 - WIN) {                  // cold path row 1
            m1 = fmaxf(m1, pm1);
            const float sv[8] = {w0, w1, w2, w3, w4, w5, w6, w7};
#pragma unroll
            for (int j = 0; j < 8; j++)
                if (sv[j] > m1 - WIN)
                    emit32(buf1, cnt1, zs, q, a1, b1, c1, m1, 2 * p + j);
        }
    }

    finalize_row(zs, buf0, cnt0, m0, q, g, row0, a0, b0, c0, out);
    finalize_row(zs, buf1, cnt1, m1, q, g, row1, a1, b1, c1, out);
}

// ---------------------------------------------------------------------------
extern "C" void kernel_launch(void* const* d_in, const int* in_sizes, int n_in,
                              void* d_out, int out_size) {
    const float* x1 = (const float*)d_in[0];
    const float* x2 = (const float*)d_in[1];
    const float* Wq = (const float*)d_in[2];
    const float* bq = (const float*)d_in[3];
    const float* Wk = (const float*)d_in[4];
    // d_in[5] = bk: per-row constant -> cancels in softmax
    const float* Wv = (const float*)d_in[6];
    const float* bv = (const float*)d_in[7];
    float* out = (float*)d_out;

    precompute_kernel<<<(NHEAD * PAIRS + 255) / 256, 256>>>(x1, x2, Wq, bq, Wk, Wv, bv);

    const int smem = 2 * PAIRS * (int)sizeof(float4)              // 64 KB z
                   + 256 * 2 * CAP * (int)sizeof(unsigned short); // 10 KB buffers
    cudaFuncSetAttribute(attn_kernel, cudaFuncAttributeMaxDynamicSharedMemorySize, smem);
    dim3 grid(SEQ / 128, NHEAD);
    attn_kernel<<<grid, 256, smem>>>(x1, out);
}

// round 11
// speedup vs baseline: 1.6024x; 1.1044x over previous
#include <cuda_runtime.h>

#define NHEAD  8
#define SEQ    4096
#define DH     8
#define PAIRS  2048              // t-pairs per head
#define HPAIRS 1024              // t-pairs per half (split-KV x2)
#define CAP    10                // deferred-entry slots per (thread,row)
#define WIN    20.0f             // window: dropped terms < 4096*e^-20 ~ 8e-6
#define NROWS  (NHEAD * SEQ)

// ---------------- __device__ scratch (no allocations allowed) ----------------
// Keys packed per half, INTERLEAVED inside each half: pair p (0..2047) of head
// g: half = p>>10, ph = p & 1023, dst = g*2048 + half*1024 + (ph&255)*4 + (ph>>8)
// so quad lane q (owning 256 pairs of the half) reads zs[p*4+q]: 64 B contiguous
// per quad + row broadcast -> conflict-free.
//  zA word: (zx_t, zx_t1, zy_t, zy_t1),  zB word: (zz_t, zz_t1, zw_t, zw_t1)
// where z_t = SCALE * ( Wq^T Wk x2_t , bq . Wk x2_t ).
__device__ float4 g_zA[NHEAD * PAIRS];
__device__ float4 g_zB[NHEAD * PAIRS];
__device__ float  g_v [NHEAD * SEQ * DH];    // v[g][t][h] = Wv x1 + bv
// Per (half, row) softmax partials: acc[8], m, l  (10 floats)
__device__ float  g_part[2 * NROWS * 10];

// ---------------------------------------------------------------------------
// Packed f32x2 helpers
// ---------------------------------------------------------------------------
__device__ __forceinline__ unsigned long long fma2(unsigned long long a,
                                                   unsigned long long b,
                                                   unsigned long long c) {
    unsigned long long d;
    asm("fma.rn.f32x2 %0, %1, %2, %3;" : "=l"(d) : "l"(a), "l"(b), "l"(c));
    return d;
}
__device__ __forceinline__ unsigned long long pack2(float x, float y) {
    unsigned long long r;
    asm("mov.b64 %0, {%1, %2};" : "=l"(r) : "f"(x), "f"(y));
    return r;
}
__device__ __forceinline__ void unpack2(unsigned long long v, float& x, float& y) {
    asm("mov.b64 {%0, %1}, %2;" : "=f"(x), "=f"(y) : "l"(v));
}

// ---------------------------------------------------------------------------
// Precompute: one thread per (g, pair p).
// ---------------------------------------------------------------------------
__device__ __forceinline__ float4 eff_key(const float X2[3],
                                          const float* __restrict__ Wq,
                                          const float* __restrict__ bq,
                                          const float* __restrict__ Wk) {
    const float SCALEF = 1448.1546878700492f;  // 2^10.5
    float y0 = 0.f, y1 = 0.f, y2 = 0.f, w = 0.f;
#pragma unroll
    for (int h = 0; h < 8; h++) {
        float u = fmaf(Wk[h * 3 + 0], X2[0],
                  fmaf(Wk[h * 3 + 1], X2[1], Wk[h * 3 + 2] * X2[2]));
        y0 = fmaf(Wq[h * 3 + 0], u, y0);
        y1 = fmaf(Wq[h * 3 + 1], u, y1);
        y2 = fmaf(Wq[h * 3 + 2], u, y2);
        w  = fmaf(bq[h], u, w);
    }
    return make_float4(SCALEF * y0, SCALEF * y1, SCALEF * y2, SCALEF * w);
}

__global__ void precompute_kernel(const float* __restrict__ x1,
                                  const float* __restrict__ x2,
                                  const float* __restrict__ Wq,
                                  const float* __restrict__ bq,
                                  const float* __restrict__ Wk,
                                  const float* __restrict__ Wv,
                                  const float* __restrict__ bv) {
    int i = blockIdx.x * blockDim.x + threadIdx.x;   // i = g*PAIRS + p
    if (i >= NHEAD * PAIRS) return;
    const int g = i >> 11;
    const int p = i & (PAIRS - 1);
    const int r0 = g * SEQ + 2 * p;

    float X2a[3], X2b[3], X1a[3], X1b[3];
#pragma unroll
    for (int j = 0; j < 3; j++) {
        X2a[j] = x2[r0 * 3 + j];       X2b[j] = x2[(r0 + 1) * 3 + j];
        X1a[j] = x1[r0 * 3 + j];       X1b[j] = x1[(r0 + 1) * 3 + j];
    }
    const float4 za = eff_key(X2a, Wq, bq, Wk);
    const float4 zb = eff_key(X2b, Wq, bq, Wk);

    const int ph  = p & (HPAIRS - 1);
    const int dst = g * PAIRS + (p >> 10) * HPAIRS + ((ph & 255) << 2) + (ph >> 8);
    g_zA[dst] = make_float4(za.x, zb.x, za.y, zb.y);
    g_zB[dst] = make_float4(za.z, zb.z, za.w, zb.w);

#pragma unroll
    for (int h = 0; h < 8; h++) {
        g_v[(size_t)r0 * 8 + h] =
            fmaf(Wv[h * 3 + 0], X1a[0], fmaf(Wv[h * 3 + 1], X1a[1],
            fmaf(Wv[h * 3 + 2], X1a[2], bv[h])));
        g_v[(size_t)(r0 + 1) * 8 + h] =
            fmaf(Wv[h * 3 + 0], X1b[0], fmaf(Wv[h * 3 + 1], X1b[1],
            fmaf(Wv[h * 3 + 2], X1b[2], bv[h])));
    }
}

// ---------------------------------------------------------------------------
// Threefry2x32, partitionable mode: word(i) = x0^x1 of counter (0, i),
// key (0, 42). keep <=> MSB == 0.
// ---------------------------------------------------------------------------
__device__ __forceinline__ unsigned rotl32(unsigned x, int r) {
    return __funnelshift_l(x, x, r);
}
__device__ __forceinline__ unsigned threefry_word(unsigned idx) {
    const unsigned K1 = 42u;
    const unsigned K2 = 0x1BD11BF0u;
    unsigned x0 = 0u;
    unsigned x1 = idx + K1;
#define TF_R(r)  { x0 += x1; x1 = rotl32(x1, r); x1 ^= x0; }
#define TF_G(a,b,c,d,j0,j1) TF_R(a) TF_R(b) TF_R(c) TF_R(d) x0 += (j0); x1 += (j1);
    TF_G(13, 15, 26,  6, K1,       K2 + 1u)
    TF_G(17, 29, 16, 24, K2,       0u + 2u)
    TF_G(13, 15, 26,  6, 0u,       K1 + 3u)
    TF_G(17, 29, 16, 24, K1,       K2 + 4u)
    TF_G(13, 15, 26,  6, K2,       0u + 5u)
#undef TF_G
#undef TF_R
    return x0 ^ x1;
}

// Exact fp32 re-score of lane-local t (0..511) from smem (same FMA chain as
// the scan -> bit-identical values).
__device__ __forceinline__ float score_at(const float4* __restrict__ zs, int q,
                                          int tloc, float a, float b, float c) {
    const int idx = ((tloc >> 1) << 2) + q;
    const float4 A = zs[idx];
    const float4 B = zs[HPAIRS + idx];
    const bool odd = (tloc & 1);
    const float zx = odd ? A.y : A.x;
    const float zy = odd ? A.w : A.z;
    const float zz = odd ? B.y : B.x;
    const float zw = odd ? B.w : B.z;
    return fmaf(a, zx, fmaf(b, zy, fmaf(c, zz, zw)));
}

__device__ __forceinline__ void emit32(unsigned short* buf, int& cnt,
                                       const float4* __restrict__ zs, int q,
                                       float a, float b, float c,
                                       float m, int tl) {
    if (cnt == CAP) {                       // prune entries below current window
        int k = 0;
        for (int i = 0; i < CAP; i++) {
            const int t2 = buf[i];
            if (score_at(zs, q, t2, a, b, c) > m - WIN)
                buf[k++] = (unsigned short)t2;
        }
        cnt = k;
        if (cnt == CAP) cnt = CAP - 1;      // ~impossible; keep newest
    }
    buf[cnt++] = (unsigned short)tl;
}

// Phase 2 + quad merge; writes (acc[8], m, l) partial for (half, row).
__device__ __forceinline__ void finalize_row(const float4* __restrict__ zs,
                                             const unsigned short* buf, int cnt,
                                             float m, int q, int g, int half,
                                             int row, float a, float b, float c) {
    const int tbase = half * 2048 + (q << 9);          // global t of lane's range
    const float* vg = g_v + ((size_t)g * SEQ + tbase) * DH;
    const unsigned rowbase = ((unsigned)row << 12) + (unsigned)tbase;
    const float M = m;
    float l = 0.f;
    float acc0 = 0.f, acc1 = 0.f, acc2 = 0.f, acc3 = 0.f;
    float acc4 = 0.f, acc5 = 0.f, acc6 = 0.f, acc7 = 0.f;
    for (int i = 0; i < cnt; i++) {
        const int tloc = buf[i];
        const float sc = score_at(zs, q, tloc, a, b, c);
        if (sc > M - WIN) {
            const float e = __expf(sc - M);
            l += e;                                    // denominator: mask-free
            const unsigned w = threefry_word(rowbase + (unsigned)tloc);
            if (!(w & 0x80000000u)) {                  // keep (u < 0.5)
                const float4* vp =
                    reinterpret_cast<const float4*>(vg + (size_t)tloc * DH);
                const float4 va = vp[0];
                const float4 vb = vp[1];
                acc0 = fmaf(e, va.x, acc0);
                acc1 = fmaf(e, va.y, acc1);
                acc2 = fmaf(e, va.z, acc2);
                acc3 = fmaf(e, va.w, acc3);
                acc4 = fmaf(e, vb.x, acc4);
                acc5 = fmaf(e, vb.y, acc5);
                acc6 = fmaf(e, vb.z, acc6);
                acc7 = fmaf(e, vb.w, acc7);
            }
        }
    }
    // quad merge (lanes xor 1, 2 share a row)
    float Mq = M;
    Mq = fmaxf(Mq, __shfl_xor_sync(0xffffffffu, Mq, 1));
    Mq = fmaxf(Mq, __shfl_xor_sync(0xffffffffu, Mq, 2));
    const float f = __expf(M - Mq);
    l *= f;
    acc0 *= f; acc1 *= f; acc2 *= f; acc3 *= f;
    acc4 *= f; acc5 *= f; acc6 *= f; acc7 *= f;
#pragma unroll
    for (int d = 1; d <= 2; d <<= 1) {
        l    += __shfl_xor_sync(0xffffffffu, l,    d);
        acc0 += __shfl_xor_sync(0xffffffffu, acc0, d);
        acc1 += __shfl_xor_sync(0xffffffffu, acc1, d);
        acc2 += __shfl_xor_sync(0xffffffffu, acc2, d);
        acc3 += __shfl_xor_sync(0xffffffffu, acc3, d);
        acc4 += __shfl_xor_sync(0xffffffffu, acc4, d);
        acc5 += __shfl_xor_sync(0xffffffffu, acc5, d);
        acc6 += __shfl_xor_sync(0xffffffffu, acc6, d);
        acc7 += __shfl_xor_sync(0xffffffffu, acc7, d);
    }
    float* part = g_part + ((size_t)half * NROWS + row) * 10;
    const float oc[8] = {acc0, acc1, acc2, acc3, acc4, acc5, acc6, acc7};
    part[2 * q]     = oc[2 * q];
    part[2 * q + 1] = oc[2 * q + 1];
    if (q == 0) { part[8] = Mq; part[9] = l; }
}

// ---------------------------------------------------------------------------
// Main kernel. Grid (SEQ/128, NHEAD, 2); block = 256 threads: 64 row-slots x
// quad(4). Each thread owns TWO rows (s0, s0+64). blockIdx.z = t-half; quad
// lane q scans the half's pairs [q*256,(q+1)*256) (512 t's, 64 iterations).
// smem = 32 KB z-half + 10 KB buffers -> 5 CTAs/SM.
// ---------------------------------------------------------------------------
__global__ void __launch_bounds__(256) attn_kernel(const float* __restrict__ x1) {
    extern __shared__ char smem_raw[];
    float4* zs = reinterpret_cast<float4*>(smem_raw);             // 32 KB
    unsigned short* tb = reinterpret_cast<unsigned short*>(smem_raw + 32768);
    const int g    = blockIdx.y;
    const int half = blockIdx.z;

    const float4* srcA = g_zA + g * PAIRS + half * HPAIRS;
    const float4* srcB = g_zB + g * PAIRS + half * HPAIRS;
    for (int i = threadIdx.x; i < HPAIRS; i += 256) {
        zs[i]          = srcA[i];              // linear copy keeps interleave
        zs[HPAIRS + i] = srcB[i];
    }
    __syncthreads();

    const int q     = threadIdx.x & 3;
    const int rslot = threadIdx.x >> 2;                 // 0..63
    const int s0    = blockIdx.x * 128 + rslot;
    const int s1    = s0 + 64;
    const int row0  = g * SEQ + s0;
    const int row1  = g * SEQ + s1;

    const float a0 = x1[row0 * 3 + 0], b0 = x1[row0 * 3 + 1], c0 = x1[row0 * 3 + 2];
    const float a1 = x1[row1 * 3 + 0], b1 = x1[row1 * 3 + 1], c1 = x1[row1 * 3 + 2];
    const unsigned long long aa0 = pack2(a0, a0), bb0 = pack2(b0, b0), cc0 = pack2(c0, c0);
    const unsigned long long aa1 = pack2(a1, a1), bb1 = pack2(b1, b1), cc1 = pack2(c1, c1);

    unsigned short* buf0 = tb + threadIdx.x * (2 * CAP);
    unsigned short* buf1 = buf0 + CAP;
    int cnt0 = 0, cnt1 = 0;

    const ulonglong2* ZA = reinterpret_cast<const ulonglong2*>(zs) + q;
    const ulonglong2* ZB = ZA + HPAIRS;

    float m0 = -3.0e38f, m1 = -3.0e38f;

    for (int p = 0; p < 256; p += 4) {         // 8 t's x 2 rows per iteration
        const ulonglong2 A0 = ZA[(p + 0) << 2], B0 = ZB[(p + 0) << 2];
        const ulonglong2 A1 = ZA[(p + 1) << 2], B1 = ZB[(p + 1) << 2];
        const ulonglong2 A2 = ZA[(p + 2) << 2], B2 = ZB[(p + 2) << 2];
        const ulonglong2 A3 = ZA[(p + 3) << 2], B3 = ZB[(p + 3) << 2];

        const unsigned long long R00 = fma2(aa0, A0.x, fma2(bb0, A0.y, fma2(cc0, B0.x, B0.y)));
        const unsigned long long R01 = fma2(aa0, A1.x, fma2(bb0, A1.y, fma2(cc0, B1.x, B1.y)));
        const unsigned long long R02 = fma2(aa0, A2.x, fma2(bb0, A2.y, fma2(cc0, B2.x, B2.y)));
        const unsigned long long R03 = fma2(aa0, A3.x, fma2(bb0, A3.y, fma2(cc0, B3.x, B3.y)));
        const unsigned long long R10 = fma2(aa1, A0.x, fma2(bb1, A0.y, fma2(cc1, B0.x, B0.y)));
        const unsigned long long R11 = fma2(aa1, A1.x, fma2(bb1, A1.y, fma2(cc1, B1.x, B1.y)));
        const unsigned long long R12 = fma2(aa1, A2.x, fma2(bb1, A2.y, fma2(cc1, B2.x, B2.y)));
        const unsigned long long R13 = fma2(aa1, A3.x, fma2(bb1, A3.y, fma2(cc1, B3.x, B3.y)));

        float u0, u1, u2, u3, u4, u5, u6, u7;
        unpack2(R00, u0, u1); unpack2(R01, u2, u3);
        unpack2(R02, u4, u5); unpack2(R03, u6, u7);
        const float pm0 = fmaxf(fmaxf(fmaxf(u0, u1), fmaxf(u2, u3)),
                                fmaxf(fmaxf(u4, u5), fmaxf(u6, u7)));

        float w0, w1, w2, w3, w4, w5, w6, w7;
        unpack2(R10, w0, w1); unpack2(R11, w2, w3);
        unpack2(R12, w4, w5); unpack2(R13, w6, w7);
        const float pm1 = fmaxf(fmaxf(fmaxf(w0, w1), fmaxf(w2, w3)),
                                fmaxf(fmaxf(w4, w5), fmaxf(w6, w7)));

        if (pm0 > m0 - WIN) {                  // cold path row 0
            m0 = fmaxf(m0, pm0);
            const float sv[8] = {u0, u1, u2, u3, u4, u5, u6, u7};
#pragma unroll
            for (int j = 0; j < 8; j++)
                if (sv[j] > m0 - WIN)
                    emit32(buf0, cnt0, zs, q, a0, b0, c0, m0, 2 * p + j);
        }
        if (pm1 > m1 - WIN) {                  // cold path row 1
            m1 = fmaxf(m1, pm1);
            const float sv[8] = {w0, w1, w2, w3, w4, w5, w6, w7};
#pragma unroll
            for (int j = 0; j < 8; j++)
                if (sv[j] > m1 - WIN)
                    emit32(buf1, cnt1, zs, q, a1, b1, c1, m1, 2 * p + j);
        }
    }

    finalize_row(zs, buf0, cnt0, m0, q, g, half, row0, a0, b0, c0);
    finalize_row(zs, buf1, cnt1, m1, q, g, half, row1, a1, b1, c1);
}

// ---------------------------------------------------------------------------
// Merge the two t-halves per row: exact cross-half softmax combine + output.
// ---------------------------------------------------------------------------
__global__ void merge_kernel(float* __restrict__ out) {
    const int row = blockIdx.x * blockDim.x + threadIdx.x;
    if (row >= NROWS) return;
    const float* p0 = g_part + (size_t)row * 10;
    const float* p1 = g_part + ((size_t)NROWS + row) * 10;
    const float m0 = p0[8], l0 = p0[9];
    const float m1 = p1[8], l1 = p1[9];
    const float M  = fmaxf(m0, m1);
    const float f0 = __expf(m0 - M);
    const float f1 = __expf(m1 - M);
    const float l  = fmaf(f0, l0, f1 * l1);
    const float inv = 2.0f / l;                        // dropout 1/(1-p) = 2
#pragma unroll
    for (int h = 0; h < 8; h++)
        out[(size_t)row * DH + h] = fmaf(f0, p0[h], f1 * p1[h]) * inv;
}

// ---------------------------------------------------------------------------
extern "C" void kernel_launch(void* const* d_in, const int* in_sizes, int n_in,
                              void* d_out, int out_size) {
    const float* x1 = (const float*)d_in[0];
    const float* x2 = (const float*)d_in[1];
    const float* Wq = (const float*)d_in[2];
    const float* bq = (const float*)d_in[3];
    const float* Wk = (const float*)d_in[4];
    // d_in[5] = bk: per-row constant -> cancels in softmax
    const float* Wv = (const float*)d_in[6];
    const float* bv = (const float*)d_in[7];
    float* out = (float*)d_out;

    precompute_kernel<<<(NHEAD * PAIRS + 255) / 256, 256>>>(x1, x2, Wq, bq, Wk, Wv, bv);

    const int smem = 2 * HPAIRS * (int)sizeof(float4)             // 32 KB z-half
                   + 256 * 2 * CAP * (int)sizeof(unsigned short); // 10 KB buffers
    cudaFuncSetAttribute(attn_kernel, cudaFuncAttributeMaxDynamicSharedMemorySize, smem);
    dim3 grid(SEQ / 128, NHEAD, 2);
    attn_kernel<<<grid, 256, smem>>>(x1);

    merge_kernel<<<(NROWS + 255) / 256, 256>>>(out);
}